// round 9
// baseline (speedup 1.0000x reference)
#include <cuda_runtime.h>
#include <math.h>

// ---------------------------------------------------------------------------
// GLSDE R7: unit-ownership encoder (R6 with dot-index fix).
// 256 thr = 64 units x 4 k-quarters. Thread (u,q) computes gate rows
// {u, u+64, u+128} over k=[16q,16q+16); shfl.bfly reduce-scatter -> lane q
// owns batch row bt=q; nonlin fully parallel; double-buffered h; ONE barrier.
// Output: [x_recon (B*T) | mu (B*16) | log_var (B*16)] float32
// ---------------------------------------------------------------------------

#define BSZ 2048
#define TLEN 512
#define IND 6
#define HID 64
#define LAT 16
#define BT 4
#define NTHR 256
#define KQ 16
#define HPAD 72   // padded h row

typedef unsigned long long u64;

__device__ float g_hT[BSZ * HID];
__device__ float g_xg[BSZ * 3];

__device__ __forceinline__ u64 pack2(float lo, float hi) {
    u64 r; asm("mov.b64 %0, {%1,%2};" : "=l"(r) : "f"(lo), "f"(hi)); return r;
}
__device__ __forceinline__ void unpack2(u64 v, float& lo, float& hi) {
    asm("mov.b64 {%0,%1}, %2;" : "=f"(lo), "=f"(hi) : "l"(v));
}
__device__ __forceinline__ void ffma2(u64& d, u64 a, u64 b) {
    asm("fma.rn.f32x2 %0, %1, %2, %0;" : "+l"(d) : "l"(a), "l"(b));
}
__device__ __forceinline__ float sig_fast(float v) {
    return __fdividef(1.0f, 1.0f + __expf(-v));
}
__device__ __forceinline__ float tanh_fast(float x) {
    float t = __expf(-2.0f * fabsf(x));
    return copysignf(__fdividef(1.0f - t, 1.0f + t), x);
}

// ---------------------------------------------------------------------------
// Kernel A: encoder GRU scan.
// ---------------------------------------------------------------------------
__global__ void __launch_bounds__(NTHR, 3) enc_kernel(
    const float* __restrict__ x,
    const float* __restrict__ Wih, const float* __restrict__ Whh,
    const float* __restrict__ bih, const float* __restrict__ bhh)
{
    const int tid = threadIdx.x;
    const int u   = tid >> 2;          // hidden unit 0..63
    const int q   = tid & 3;           // k-quarter / owned batch row
    const int b0  = blockIdx.x * BT;

    __shared__ __align__(16) float h_sh[2][BT][HPAD];
    __shared__ __align__(16) float x_sh[2][BT][8];

    // Whh slices: 3 gate rows x 16 k; w2[g][k] = packed pair at float
    // offsets (2k, 2k+1) within this thread's 16-wide k-quarter.
    u64 w2[3][KQ / 2];
#pragma unroll
    for (int g = 0; g < 3; g++) {
        const u64* wp = (const u64*)(Whh + (size_t)(g * HID + u) * HID + q * KQ);
#pragma unroll
        for (int k = 0; k < KQ / 2; k++) w2[g][k] = wp[k];
    }
    // Wih rows for this unit's 3 gates (used post-shuffle on own bt only)
    u64 wxr[3], wxz[3], wxn[3];
#pragma unroll
    for (int j = 0; j < 3; j++) {
        wxr[j] = pack2(Wih[(0 * HID + u) * IND + 2 * j], Wih[(0 * HID + u) * IND + 2 * j + 1]);
        wxz[j] = pack2(Wih[(1 * HID + u) * IND + 2 * j], Wih[(1 * HID + u) * IND + 2 * j + 1]);
        wxn[j] = pack2(Wih[(2 * HID + u) * IND + 2 * j], Wih[(2 * HID + u) * IND + 2 * j + 1]);
    }
    const float b_r  = bih[u] + bhh[u];
    const float b_z  = bih[HID + u] + bhh[HID + u];
    const float b_hn = bhh[2 * HID + u];
    const float b_xn = bih[2 * HID + u];

    // init
    float h_own = 0.0f;                       // h[bt=q][u], carried in register
    for (int i = tid; i < 2 * BT * HPAD; i += NTHR) ((float*)h_sh)[i] = 0.0f;
    if (tid < BT * IND) {
        int bt = tid / IND, d = tid % IND;
        x_sh[0][bt][d] = x[(size_t)(b0 + bt) * (TLEN * IND) + d];
    }
    __syncthreads();

    const int q0 = q & 1, q1 = (q >> 1) & 1;

    for (int t = 0; t < TLEN; t++) {
        const int cur = t & 1, nxt = cur ^ 1;
        if (t + 1 < TLEN && tid < BT * IND) {
            int bt = tid / IND, d = tid % IND;
            x_sh[nxt][bt][d] = x[(size_t)(b0 + bt) * (TLEN * IND) + (t + 1) * IND + d];
        }

        // ---- h-dot: 3 gates x 4 bt, two bt-pair passes (reg pressure) ----
        float s[4][BT];
#pragma unroll
        for (int bp = 0; bp < 2; bp++) {
            u64 acc[3][2];
#pragma unroll
            for (int g = 0; g < 3; g++) { acc[g][0] = 0ULL; acc[g][1] = 0ULL; }
#pragma unroll
            for (int k16 = 0; k16 < 4; k16++) {        // 4 x 16B loads per bt
#pragma unroll
                for (int b2 = 0; b2 < 2; b2++) {
                    const int bt = bp * 2 + b2;
                    ulonglong2 hv =
                        ((const ulonglong2*)(&h_sh[cur][bt][q * KQ]))[k16];
#pragma unroll
                    for (int g = 0; g < 3; g++) {
                        ffma2(acc[g][b2], w2[g][2 * k16 + 0], hv.x);
                        ffma2(acc[g][b2], w2[g][2 * k16 + 1], hv.y);
                    }
                }
            }
#pragma unroll
            for (int g = 0; g < 3; g++)
#pragma unroll
                for (int b2 = 0; b2 < 2; b2++) {
                    float lo, hi; unpack2(acc[g][b2], lo, hi);
                    s[g][bp * 2 + b2] = lo + hi;
                }
            s[3][bp * 2 + 0] = 0.0f; s[3][bp * 2 + 1] = 0.0f;
        }

        // ---- reduce-scatter over the 4 q-lanes (xor1 then xor2) ----
        float t0[4], t1[4];
#pragma unroll
        for (int g = 0; g < 4; g++) {
            float keep0 = q0 ? s[g][1] : s[g][0];
            float send0 = q0 ? s[g][0] : s[g][1];
            float keep1 = q0 ? s[g][3] : s[g][2];
            float send1 = q0 ? s[g][2] : s[g][3];
            t0[g] = keep0 + __shfl_xor_sync(0xffffffffu, send0, 1);
            t1[g] = keep1 + __shfl_xor_sync(0xffffffffu, send1, 1);
        }
        float f[4];
#pragma unroll
        for (int g = 0; g < 4; g++) {
            float keep = q1 ? t1[g] : t0[g];
            float send = q1 ? t0[g] : t1[g];
            f[g] = keep + __shfl_xor_sync(0xffffffffu, send, 2);
        }

        // ---- inject biases + x-dots for own bt (=q) ----
        {
            const u64* xp = (const u64*)x_sh[cur][q];
            u64 ar = 0ULL, az = 0ULL, an = 0ULL;
#pragma unroll
            for (int j = 0; j < 3; j++) {
                ffma2(ar, wxr[j], xp[j]);
                ffma2(az, wxz[j], xp[j]);
                ffma2(an, wxn[j], xp[j]);
            }
            float lo, hi;
            unpack2(ar, lo, hi); f[0] += b_r + lo + hi;
            unpack2(az, lo, hi); f[1] += b_z + lo + hi;
            f[2] += b_hn;
            unpack2(an, lo, hi); f[3] += b_xn + lo + hi;
        }

        // ---- nonlin for (u, bt=q) ----
        {
            float r  = sig_fast(f[0]);
            float zg = sig_fast(f[1]);
            float n  = tanh_fast(fmaf(r, f[2], f[3]));
            h_own = (1.0f - zg) * n + zg * h_own;
            h_sh[nxt][q][u] = h_own;
        }
        __syncthreads();
    }

    g_hT[(size_t)(b0 + q) * HID + u] = h_own;
}

// ---------------------------------------------------------------------------
// Kernel B: per-batch: mu/lv heads, z0, RK4(64), decoder fc + x-gates.
// ---------------------------------------------------------------------------
__global__ void __launch_bounds__(32) mid_kernel(
    const float* __restrict__ fc_mu_W, const float* __restrict__ fc_mu_b,
    const float* __restrict__ fc_lv_W, const float* __restrict__ fc_lv_b,
    const float* __restrict__ ode_W,   const float* __restrict__ ode_b,
    const float* __restrict__ dec_fc_W, const float* __restrict__ dec_fc_b,
    const float* __restrict__ dec_Wih, const float* __restrict__ dec_bih,
    float* __restrict__ out_mu, float* __restrict__ out_lv)
{
    __shared__ __align__(16) float sMu[LAT * HID], sLv[LAT * HID], sDW[HID * LAT];
    __shared__ __align__(16) float sOW[LAT * LAT], sWih[3 * HID];
    __shared__ float sOb[LAT], sMub[LAT], sLvb[LAT], sDb[HID], sBih[3];

    const int tid = threadIdx.x;
    for (int i = tid; i < LAT * HID; i += 32) {
        sMu[i] = fc_mu_W[i]; sLv[i] = fc_lv_W[i]; sDW[i] = dec_fc_W[i];
    }
    for (int i = tid; i < LAT * LAT; i += 32) sOW[i] = ode_W[i];
    for (int i = tid; i < 3 * HID;  i += 32) sWih[i] = dec_Wih[i];
    if (tid < LAT) { sOb[tid] = ode_b[tid]; sMub[tid] = fc_mu_b[tid]; sLvb[tid] = fc_lv_b[tid]; }
    if (tid < 3)   sBih[tid] = dec_bih[tid];
    for (int i = tid; i < HID; i += 32) sDb[i] = dec_fc_b[i];
    __syncthreads();

    const int b = blockIdx.x * 32 + tid;
    if (b >= BSZ) return;

    u64 hv2[HID / 2];
    const u64* hvp = (const u64*)(g_hT + (size_t)b * HID);
#pragma unroll
    for (int k = 0; k < HID / 2; k++) hv2[k] = hvp[k];

    const u64* sMu2 = (const u64*)sMu;
    const u64* sLv2 = (const u64*)sLv;
    const u64* sOW2 = (const u64*)sOW;
    const u64* sDW2 = (const u64*)sDW;

    float z[LAT];
#pragma unroll
    for (int i = 0; i < LAT; i++) {
        u64 am = 0ULL, al = 0ULL;
#pragma unroll
        for (int k = 0; k < HID / 2; k++) {
            ffma2(am, sMu2[i * (HID / 2) + k], hv2[k]);
            ffma2(al, sLv2[i * (HID / 2) + k], hv2[k]);
        }
        float m0, m1, l0, l1;
        unpack2(am, m0, m1); unpack2(al, l0, l1);
        float m = sMub[i] + m0 + m1;
        float l = sLvb[i] + l0 + l1;
        out_mu[(size_t)b * LAT + i] = m;
        out_lv[(size_t)b * LAT + i] = l;
        z[i] = m + expf(0.5f * l);
    }

    const float hs = 1.0f / 64.0f;
    float k1[LAT], k2[LAT], k3[LAT], k4[LAT], zt[LAT];

#define ODE_EVAL(SRC, DST)                                                    \
    {                                                                         \
        u64 zp[LAT / 2];                                                      \
        _Pragma("unroll")                                                     \
        for (int m = 0; m < LAT / 2; m++)                                     \
            zp[m] = pack2(SRC[2 * m], SRC[2 * m + 1]);                        \
        _Pragma("unroll")                                                     \
        for (int i = 0; i < LAT; i++) {                                       \
            u64 a = 0ULL;                                                     \
            _Pragma("unroll")                                                 \
            for (int j = 0; j < LAT / 2; j++)                                 \
                ffma2(a, sOW2[i * (LAT / 2) + j], zp[j]);                     \
            float lo, hi; unpack2(a, lo, hi);                                 \
            DST[i] = fmaxf(sOb[i] + lo + hi, 0.0f);                           \
        }                                                                     \
    }

    for (int s = 0; s < 64; s++) {
        ODE_EVAL(z, k1);
#pragma unroll
        for (int i = 0; i < LAT; i++) zt[i] = fmaf(0.5f * hs, k1[i], z[i]);
        ODE_EVAL(zt, k2);
#pragma unroll
        for (int i = 0; i < LAT; i++) zt[i] = fmaf(0.5f * hs, k2[i], z[i]);
        ODE_EVAL(zt, k3);
#pragma unroll
        for (int i = 0; i < LAT; i++) zt[i] = fmaf(hs, k3[i], z[i]);
        ODE_EVAL(zt, k4);
#pragma unroll
        for (int i = 0; i < LAT; i++)
            z[i] += (hs / 6.0f) * (k1[i] + 2.0f * k2[i] + 2.0f * k3[i] + k4[i]);
    }

    u64 zp[LAT / 2];
#pragma unroll
    for (int m = 0; m < LAT / 2; m++) zp[m] = pack2(z[2 * m], z[2 * m + 1]);

    float xg0 = sBih[0], xg1 = sBih[1], xg2 = sBih[2];
#pragma unroll
    for (int j = 0; j < HID; j++) {
        u64 a = 0ULL;
#pragma unroll
        for (int i = 0; i < LAT / 2; i++) ffma2(a, sDW2[j * (LAT / 2) + i], zp[i]);
        float lo, hi; unpack2(a, lo, hi);
        float av = fmaxf(sDb[j] + lo + hi, 0.0f);
        xg0 = fmaf(sWih[0 * HID + j], av, xg0);
        xg1 = fmaf(sWih[1 * HID + j], av, xg1);
        xg2 = fmaf(sWih[2 * HID + j], av, xg2);
    }
    g_xg[(size_t)b * 3 + 0] = xg0;
    g_xg[(size_t)b * 3 + 1] = xg1;
    g_xg[(size_t)b * 3 + 2] = xg2;
}

// ---------------------------------------------------------------------------
// Kernel C: decoder GRU, hidden size 1, constant input gates. Thread per batch.
// ---------------------------------------------------------------------------
__global__ void __launch_bounds__(64) dec_kernel(
    const float* __restrict__ dec_Whh, const float* __restrict__ dec_bhh,
    float* __restrict__ out)
{
    const int b = blockIdx.x * 64 + threadIdx.x;
    if (b >= BSZ) return;

    const float xr = g_xg[(size_t)b * 3 + 0];
    const float xz = g_xg[(size_t)b * 3 + 1];
    const float xn = g_xg[(size_t)b * 3 + 2];
    const float w0 = dec_Whh[0], w1 = dec_Whh[1], w2 = dec_Whh[2];
    const float c0 = dec_bhh[0], c1 = dec_bhh[1], c2 = dec_bhh[2];

    float h = 0.0f;
    float4* outp = (float4*)(out + (size_t)b * TLEN);
    for (int t = 0; t < TLEN; t += 4) {
        float4 buf;
        float* bf = (float*)&buf;
#pragma unroll
        for (int qq = 0; qq < 4; qq++) {
            float r  = sig_fast(xr + fmaf(w0, h, c0));
            float zg = sig_fast(xz + fmaf(w1, h, c1));
            float n  = tanh_fast(xn + r * fmaf(w2, h, c2));
            h = (1.0f - zg) * n + zg * h;
            bf[qq] = h;
        }
        outp[t >> 2] = buf;
    }
}

// ---------------------------------------------------------------------------
extern "C" void kernel_launch(void* const* d_in, const int* in_sizes, int n_in,
                              void* d_out, int out_size)
{
    const float* x        = (const float*)d_in[0];
    const float* enc_Wih  = (const float*)d_in[1];
    const float* enc_Whh  = (const float*)d_in[2];
    const float* enc_bih  = (const float*)d_in[3];
    const float* enc_bhh  = (const float*)d_in[4];
    const float* fc_mu_W  = (const float*)d_in[5];
    const float* fc_mu_b  = (const float*)d_in[6];
    const float* fc_lv_W  = (const float*)d_in[7];
    const float* fc_lv_b  = (const float*)d_in[8];
    const float* ode_W    = (const float*)d_in[9];
    const float* ode_b    = (const float*)d_in[10];
    const float* dec_fc_W = (const float*)d_in[11];
    const float* dec_fc_b = (const float*)d_in[12];
    const float* dec_Wih  = (const float*)d_in[13];
    const float* dec_Whh  = (const float*)d_in[14];
    const float* dec_bih  = (const float*)d_in[15];
    const float* dec_bhh  = (const float*)d_in[16];

    float* out = (float*)d_out;
    float* out_xrec = out;                       // B*T
    float* out_mu   = out + (size_t)BSZ * TLEN;  // B*16
    float* out_lv   = out_mu + (size_t)BSZ * LAT;

    enc_kernel<<<BSZ / BT, NTHR>>>(x, enc_Wih, enc_Whh, enc_bih, enc_bhh);
    mid_kernel<<<BSZ / 32, 32>>>(fc_mu_W, fc_mu_b, fc_lv_W, fc_lv_b,
                                 ode_W, ode_b, dec_fc_W, dec_fc_b,
                                 dec_Wih, dec_bih, out_mu, out_lv);
    dec_kernel<<<BSZ / 64, 64>>>(dec_Whh, dec_bhh, out_xrec);
}